// round 1
// baseline (speedup 1.0000x reference)
#include <cuda_runtime.h>
#include <math.h>

// Problem constants
#define M_ROWS 16384            // b * h * w = 4*64*64
#define C_DIM  180
#define NHEAD  6
#define DHEAD  30
#define WS     16
#define OWS    24
#define NKEY   (OWS*OWS)        // 576
#define NQ     (WS*WS)          // 256

// ---------------- scratch (device globals; no allocation allowed) -----------
__device__ float g_xn  [M_ROWS * C_DIM];
__device__ float g_yn  [M_ROWS * C_DIM];
__device__ float g_kv  [M_ROWS * 2 * C_DIM];
__device__ float g_q   [M_ROWS * C_DIM];
__device__ float g_attn[M_ROWS * C_DIM];
__device__ float g_xo  [M_ROWS * C_DIM];
__device__ float g_xn2 [M_ROWS * C_DIM];
__device__ float g_h1  [M_ROWS * 4 * C_DIM];
__device__ float g_bias[NHEAD * NKEY * NQ];   // [head][ki][qi] transposed for coalesced reads

// ---------------- LayerNorm: one warp per row (C=180) -----------------------
__global__ void __launch_bounds__(256) ln_kernel(
    const float* __restrict__ x, const float* __restrict__ g,
    const float* __restrict__ b, float* __restrict__ out)
{
    int row  = blockIdx.x * 8 + (threadIdx.x >> 5);
    int lane = threadIdx.x & 31;
    const float* xr = x + (size_t)row * C_DIM;
    float v[6];
    float s = 0.f;
    #pragma unroll
    for (int i = 0; i < 6; i++) {
        int idx = lane + 32 * i;
        v[i] = (idx < C_DIM) ? xr[idx] : 0.f;
        s += v[i];
    }
    #pragma unroll
    for (int o = 16; o > 0; o >>= 1) s += __shfl_xor_sync(0xffffffffu, s, o);
    float mean = s * (1.f / C_DIM);
    float s2 = 0.f;
    #pragma unroll
    for (int i = 0; i < 6; i++) {
        int idx = lane + 32 * i;
        float d = (idx < C_DIM) ? (v[i] - mean) : 0.f;
        s2 += d * d;
    }
    #pragma unroll
    for (int o = 16; o > 0; o >>= 1) s2 += __shfl_xor_sync(0xffffffffu, s2, o);
    float r = rsqrtf(s2 * (1.f / C_DIM) + 1e-5f);
    float* orow = out + (size_t)row * C_DIM;
    #pragma unroll
    for (int i = 0; i < 6; i++) {
        int idx = lane + 32 * i;
        if (idx < C_DIM) orow[idx] = (v[i] - mean) * r * g[idx] + b[idx];
    }
}

// ---------------- bias precompute: biasT[h][ki][qi] = rpb[rpi[qi,ki], h] ----
__global__ void __launch_bounds__(256) bias_kernel(
    const int* __restrict__ rpi, const float* __restrict__ rpb,
    float* __restrict__ biasT)
{
    int idx = blockIdx.x * 256 + threadIdx.x;   // over NQ*NKEY
    if (idx >= NQ * NKEY) return;
    int qi = idx / NKEY;
    int ki = idx - qi * NKEY;
    int r = rpi[idx];
    #pragma unroll
    for (int h = 0; h < NHEAD; h++)
        biasT[((size_t)h * NKEY + ki) * NQ + qi] = rpb[r * NHEAD + h];
}

// ---------------- generic fp32 GEMM: C[M,N] = A[M,K] @ W[N,K]^T + bias ------
// EP: 0 = none, 1 = +res, 2 = exact GELU
// BM=BN=64, BK=36 (180 = 5*36, 720 = 20*36 -> no K tail), 256 threads, 4x4/thr
template<int EP>
__global__ void __launch_bounds__(256) gemm_kernel(
    const float* __restrict__ A, const float* __restrict__ W,
    const float* __restrict__ bias, const float* __restrict__ res,
    float* __restrict__ C, int M, int N, int K)
{
    __shared__ float As[36][68];
    __shared__ float Wsm[36][68];
    const int bm = blockIdx.y * 64;
    const int bn = blockIdx.x * 64;
    const int t  = threadIdx.x;
    const int tx = t & 15;
    const int ty = t >> 4;

    float acc[4][4];
    #pragma unroll
    for (int i = 0; i < 4; i++)
        #pragma unroll
        for (int j = 0; j < 4; j++) acc[i][j] = 0.f;

    for (int k0 = 0; k0 < K; k0 += 36) {
        #pragma unroll
        for (int i = 0; i < 9; i++) {
            int idx = t + i * 256;      // 0..2303 over 64x36 tile
            int r = idx / 36;
            int c = idx - r * 36;
            As[c][r] = A[(size_t)(bm + r) * K + k0 + c];
            int n = bn + r;
            Wsm[c][r] = (n < N) ? W[(size_t)n * K + k0 + c] : 0.f;
        }
        __syncthreads();
        #pragma unroll
        for (int kk = 0; kk < 36; kk++) {
            float4 a4 = *(const float4*)&As[kk][ty * 4];
            float4 w4 = *(const float4*)&Wsm[kk][tx * 4];
            float a[4] = {a4.x, a4.y, a4.z, a4.w};
            float w[4] = {w4.x, w4.y, w4.z, w4.w};
            #pragma unroll
            for (int i = 0; i < 4; i++)
                #pragma unroll
                for (int j = 0; j < 4; j++)
                    acc[i][j] = fmaf(a[i], w[j], acc[i][j]);
        }
        __syncthreads();
    }

    #pragma unroll
    for (int i = 0; i < 4; i++) {
        int row = bm + ty * 4 + i;
        #pragma unroll
        for (int j = 0; j < 4; j++) {
            int col = bn + tx * 4 + j;
            if (col < N) {
                float v = acc[i][j] + bias[col];
                if (EP == 1) v += res[(size_t)row * N + col];
                if (EP == 2) v = 0.5f * v * (1.f + erff(v * 0.70710678118654752f));
                C[(size_t)row * N + col] = v;
            }
        }
    }
}

// ---------------- window attention: one block per (window, head) ------------
// 256 threads = 256 queries; K/V staged in smem (576 x 32, d padded 30->32).
// Zero-padded K/V rows outside the image still contribute exp(bias) to the
// softmax denominator (matches reference unfold-after-pad semantics).
__global__ void __launch_bounds__(256) attn_kernel(
    const float* __restrict__ q, const float* __restrict__ kv,
    const float* __restrict__ bias, float* __restrict__ out)
{
    extern __shared__ float sm[];
    float* ks = sm;               // 576*32
    float* vs = sm + NKEY * 32;   // 576*32

    const int wi   = blockIdx.x;      // 0..63  : b*16 + wy*4 + wx
    const int head = blockIdx.y;      // 0..5
    const int b  = wi >> 4;
    const int wy = (wi >> 2) & 3;
    const int wx = wi & 3;
    const int qi = threadIdx.x;

    // stage K/V for this (window, head)
    for (int idx = qi; idx < NKEY * 32; idx += 256) {
        int j  = idx >> 5;
        int dd = idx & 31;
        int jy = j / OWS;
        int jx = j - jy * OWS;
        int gy = wy * WS - 4 + jy;
        int gx = wx * WS - 4 + jx;
        float kval = 0.f, vval = 0.f;
        if (dd < DHEAD && (unsigned)gy < 64u && (unsigned)gx < 64u) {
            const float* p = kv + ((size_t)(b * 4096 + gy * 64 + gx)) * (2 * C_DIM)
                               + head * DHEAD + dd;
            kval = p[0];
            vval = p[C_DIM];
        }
        ks[idx] = kval;
        vs[idx] = vval;
    }

    // load this thread's query (scaled)
    const int iy = qi >> 4, ix = qi & 15;
    const int gy = wy * WS + iy, gx = wx * WS + ix;
    const float* qp = q + ((size_t)(b * 4096 + gy * 64 + gx)) * C_DIM + head * DHEAD;
    float qv[32];
    #pragma unroll
    for (int dd = 0; dd < DHEAD; dd++) qv[dd] = qp[dd] * 0.18257418583505537f; // 30^-0.5
    qv[30] = 0.f; qv[31] = 0.f;
    __syncthreads();

    const float* bp = bias + (size_t)head * NKEY * NQ + qi;  // [ki][qi], coalesced

    // pass 1: row max
    float m = -1e30f;
    for (int j = 0; j < NKEY; j++) {
        const float4* kr = (const float4*)(ks + j * 32);
        float s = bp[(size_t)j * NQ];
        #pragma unroll
        for (int u = 0; u < 8; u++) {
            float4 k4 = kr[u];
            s = fmaf(qv[4*u+0], k4.x, s);
            s = fmaf(qv[4*u+1], k4.y, s);
            s = fmaf(qv[4*u+2], k4.z, s);
            s = fmaf(qv[4*u+3], k4.w, s);
        }
        m = fmaxf(m, s);
    }

    // pass 2: exp + accumulate
    float acc[32];
    #pragma unroll
    for (int u = 0; u < 32; u++) acc[u] = 0.f;
    float l = 0.f;
    for (int j = 0; j < NKEY; j++) {
        const float4* kr = (const float4*)(ks + j * 32);
        float s = bp[(size_t)j * NQ];
        #pragma unroll
        for (int u = 0; u < 8; u++) {
            float4 k4 = kr[u];
            s = fmaf(qv[4*u+0], k4.x, s);
            s = fmaf(qv[4*u+1], k4.y, s);
            s = fmaf(qv[4*u+2], k4.z, s);
            s = fmaf(qv[4*u+3], k4.w, s);
        }
        float p = __expf(s - m);
        l += p;
        const float4* vr = (const float4*)(vs + j * 32);
        #pragma unroll
        for (int u = 0; u < 8; u++) {
            float4 v4 = vr[u];
            acc[4*u+0] = fmaf(p, v4.x, acc[4*u+0]);
            acc[4*u+1] = fmaf(p, v4.y, acc[4*u+1]);
            acc[4*u+2] = fmaf(p, v4.z, acc[4*u+2]);
            acc[4*u+3] = fmaf(p, v4.w, acc[4*u+3]);
        }
    }
    float inv = 1.f / l;

    // write directly in (b, h*w, c) layout (window_reverse fused)
    float* op = out + ((size_t)(b * 4096 + gy * 64 + gx)) * C_DIM + head * DHEAD;
    #pragma unroll
    for (int dd = 0; dd < DHEAD; dd++) op[dd] = acc[dd] * inv;
}

// ---------------- launch --------------------------------------------------
extern "C" void kernel_launch(void* const* d_in, const int* in_sizes, int n_in,
                              void* d_out, int out_size)
{
    const float* x      = (const float*)d_in[0];
    const float* y      = (const float*)d_in[1];
    const float* n1g    = (const float*)d_in[2];
    const float* n1b    = (const float*)d_in[3];
    const float* kv_w   = (const float*)d_in[4];
    const float* kv_b   = (const float*)d_in[5];
    const float* q_w    = (const float*)d_in[6];
    const float* q_b    = (const float*)d_in[7];
    const float* rpb    = (const float*)d_in[8];
    const float* proj_w = (const float*)d_in[9];
    const float* proj_b = (const float*)d_in[10];
    const float* n2g    = (const float*)d_in[11];
    const float* n2b    = (const float*)d_in[12];
    const float* fc1_w  = (const float*)d_in[13];
    const float* fc1_b  = (const float*)d_in[14];
    const float* fc2_w  = (const float*)d_in[15];
    const float* fc2_b  = (const float*)d_in[16];
    const int*   rpi    = (const int*)d_in[17];
    float* outp = (float*)d_out;

    float *xn, *yn, *kvp, *qp, *attnp, *xop, *xn2p, *h1p, *biasp;
    cudaGetSymbolAddress((void**)&xn,    g_xn);
    cudaGetSymbolAddress((void**)&yn,    g_yn);
    cudaGetSymbolAddress((void**)&kvp,   g_kv);
    cudaGetSymbolAddress((void**)&qp,    g_q);
    cudaGetSymbolAddress((void**)&attnp, g_attn);
    cudaGetSymbolAddress((void**)&xop,   g_xo);
    cudaGetSymbolAddress((void**)&xn2p,  g_xn2);
    cudaGetSymbolAddress((void**)&h1p,   g_h1);
    cudaGetSymbolAddress((void**)&biasp, g_bias);

    const int smem_attn = NKEY * 32 * 4 * 2;   // 147456 bytes
    cudaFuncSetAttribute(attn_kernel, cudaFuncAttributeMaxDynamicSharedMemorySize, smem_attn);

    // LN(x), LN(y)
    ln_kernel<<<M_ROWS / 8, 256>>>(x, n1g, n1b, xn);
    ln_kernel<<<M_ROWS / 8, 256>>>(y, n1g, n1b, yn);

    // bias table
    bias_kernel<<<(NQ * NKEY + 255) / 256, 256>>>(rpi, rpb, biasp);

    // kv = xn @ kv_w^T + kv_b ; q = yn @ q_w^T + q_b
    gemm_kernel<0><<<dim3(6, M_ROWS / 64), 256>>>(xn, kv_w, kv_b, nullptr, kvp,
                                                  M_ROWS, 2 * C_DIM, C_DIM);
    gemm_kernel<0><<<dim3(3, M_ROWS / 64), 256>>>(yn, q_w, q_b, nullptr, qp,
                                                  M_ROWS, C_DIM, C_DIM);

    // windowed attention
    attn_kernel<<<dim3(64, NHEAD), 256, smem_attn>>>(qp, kvp, biasp, attnp);

    // xo = attn @ proj_w^T + proj_b + x
    gemm_kernel<1><<<dim3(3, M_ROWS / 64), 256>>>(attnp, proj_w, proj_b, x, xop,
                                                  M_ROWS, C_DIM, C_DIM);

    // LN2
    ln_kernel<<<M_ROWS / 8, 256>>>(xop, n2g, n2b, xn2p);

    // h1 = gelu(xn2 @ fc1_w^T + fc1_b)
    gemm_kernel<2><<<dim3(12, M_ROWS / 64), 256>>>(xn2p, fc1_w, fc1_b, nullptr, h1p,
                                                   M_ROWS, 4 * C_DIM, C_DIM);

    // out = h1 @ fc2_w^T + fc2_b + xo
    gemm_kernel<1><<<dim3(3, M_ROWS / 64), 256>>>(h1p, fc2_w, fc2_b, xop, outp,
                                                  M_ROWS, C_DIM, 4 * C_DIM);
}

// round 2
// speedup vs baseline: 1.4222x; 1.4222x over previous
#include <cuda_runtime.h>
#include <math.h>

// Problem constants
#define M_ROWS 16384            // b * h * w = 4*64*64
#define C_DIM  180
#define NHEAD  6
#define DHEAD  30
#define WS     16
#define OWS    24
#define NKEY   (OWS*OWS)        // 576
#define NQ     (WS*WS)          // 256
#define CHUNK  144              // 576 = 4*144 ; K/V smem per chunk = 36 KB

// ---------------- scratch (device globals; no allocation allowed) -----------
__device__ float g_xn  [M_ROWS * C_DIM];
__device__ float g_yn  [M_ROWS * C_DIM];
__device__ float g_kv  [M_ROWS * 2 * C_DIM];
__device__ float g_q   [M_ROWS * C_DIM];
__device__ float g_attn[M_ROWS * C_DIM];
__device__ float g_xo  [M_ROWS * C_DIM];
__device__ float g_xn2 [M_ROWS * C_DIM];
__device__ float g_h1  [M_ROWS * 4 * C_DIM];
__device__ float g_bias[NHEAD * NKEY * NQ];   // [head][ki][qi]

// ---------------- LayerNorm: one warp per row (C=180) -----------------------
__global__ void __launch_bounds__(256) ln_kernel(
    const float* __restrict__ x, const float* __restrict__ g,
    const float* __restrict__ b, float* __restrict__ out)
{
    int row  = blockIdx.x * 8 + (threadIdx.x >> 5);
    int lane = threadIdx.x & 31;
    const float* xr = x + (size_t)row * C_DIM;
    float v[6];
    float s = 0.f;
    #pragma unroll
    for (int i = 0; i < 6; i++) {
        int idx = lane + 32 * i;
        v[i] = (idx < C_DIM) ? xr[idx] : 0.f;
        s += v[i];
    }
    #pragma unroll
    for (int o = 16; o > 0; o >>= 1) s += __shfl_xor_sync(0xffffffffu, s, o);
    float mean = s * (1.f / C_DIM);
    float s2 = 0.f;
    #pragma unroll
    for (int i = 0; i < 6; i++) {
        int idx = lane + 32 * i;
        float d = (idx < C_DIM) ? (v[i] - mean) : 0.f;
        s2 += d * d;
    }
    #pragma unroll
    for (int o = 16; o > 0; o >>= 1) s2 += __shfl_xor_sync(0xffffffffu, s2, o);
    float r = rsqrtf(s2 * (1.f / C_DIM) + 1e-5f);
    float* orow = out + (size_t)row * C_DIM;
    #pragma unroll
    for (int i = 0; i < 6; i++) {
        int idx = lane + 32 * i;
        if (idx < C_DIM) orow[idx] = (v[i] - mean) * r * g[idx] + b[idx];
    }
}

// ---------------- bias precompute: biasT[h][ki][qi] = rpb[rpi[qi,ki], h] ----
__global__ void __launch_bounds__(256) bias_kernel(
    const int* __restrict__ rpi, const float* __restrict__ rpb,
    float* __restrict__ biasT)
{
    int idx = blockIdx.x * 256 + threadIdx.x;   // over NQ*NKEY
    if (idx >= NQ * NKEY) return;
    int qi = idx / NKEY;
    int ki = idx - qi * NKEY;
    int r = rpi[idx];
    #pragma unroll
    for (int h = 0; h < NHEAD; h++)
        biasT[((size_t)h * NKEY + ki) * NQ + qi] = rpb[r * NHEAD + h];
}

// ---------------- fp32 GEMM: C[M,N] = A[M,K] @ W[N,K]^T + bias --------------
// Tile: 128 x BN x 36, per-thread 8x8, THREADS = BN*2 (BN in {64,128}).
// K is always a multiple of 36 (180 = 5*36, 720 = 20*36). M multiple of 128.
// EP: 0 = none, 1 = +res, 2 = exact GELU
template<int BN, int EP>
__global__ void __launch_bounds__(BN * 2) gemm_kernel(
    const float* __restrict__ A, const float* __restrict__ W,
    const float* __restrict__ bias, const float* __restrict__ res,
    float* __restrict__ C, int M, int N, int K)
{
    constexpr int THREADS = BN * 2;
    constexpr int TX = BN / 8;
    constexpr int A4 = 128 * 9;           // float4s in A tile (128 x 36)
    constexpr int TOT4 = (128 + BN) * 9;  // total float4s per k-chunk
    constexpr int ITER = (TOT4 + THREADS - 1) / THREADS;

    __shared__ float As[36][132];
    __shared__ float Ws[36][BN + 4];

    const int bm = blockIdx.y * 128;
    const int bn = blockIdx.x * BN;
    const int t  = threadIdx.x;
    const int tx = t % TX;
    const int ty = t / TX;

    float acc[8][8];
    #pragma unroll
    for (int i = 0; i < 8; i++)
        #pragma unroll
        for (int j = 0; j < 8; j++) acc[i][j] = 0.f;

    for (int k0 = 0; k0 < K; k0 += 36) {
        #pragma unroll
        for (int i = 0; i < ITER; i++) {
            int idx = t + i * THREADS;
            if (TOT4 % THREADS != 0 && idx >= TOT4) break;
            if (idx < A4) {
                int r = idx / 9, c4 = idx - r * 9;
                float4 v = *(const float4*)(A + (size_t)(bm + r) * K + k0 + c4 * 4);
                As[c4*4+0][r] = v.x; As[c4*4+1][r] = v.y;
                As[c4*4+2][r] = v.z; As[c4*4+3][r] = v.w;
            } else {
                int j = idx - A4;
                int r = j / 9, c4 = j - r * 9;
                int n = bn + r;
                float4 v = make_float4(0.f, 0.f, 0.f, 0.f);
                if (n < N) v = *(const float4*)(W + (size_t)n * K + k0 + c4 * 4);
                Ws[c4*4+0][r] = v.x; Ws[c4*4+1][r] = v.y;
                Ws[c4*4+2][r] = v.z; Ws[c4*4+3][r] = v.w;
            }
        }
        __syncthreads();
        #pragma unroll
        for (int kk = 0; kk < 36; kk++) {
            float a[8], w[8];
            *(float4*)&a[0] = *(const float4*)&As[kk][ty * 8];
            *(float4*)&a[4] = *(const float4*)&As[kk][ty * 8 + 4];
            *(float4*)&w[0] = *(const float4*)&Ws[kk][tx * 8];
            *(float4*)&w[4] = *(const float4*)&Ws[kk][tx * 8 + 4];
            #pragma unroll
            for (int i = 0; i < 8; i++)
                #pragma unroll
                for (int j = 0; j < 8; j++)
                    acc[i][j] = fmaf(a[i], w[j], acc[i][j]);
        }
        __syncthreads();
    }

    #pragma unroll
    for (int i = 0; i < 8; i++) {
        int row = bm + ty * 8 + i;
        #pragma unroll
        for (int j = 0; j < 8; j++) {
            int col = bn + tx * 8 + j;
            if (col < N) {
                float v = acc[i][j] + bias[col];
                if (EP == 1) v += res[(size_t)row * N + col];
                if (EP == 2) v = 0.5f * v * (1.f + erff(v * 0.70710678118654752f));
                C[(size_t)row * N + col] = v;
            }
        }
    }
}

// ---------------- window attention: one block per (window, head) ------------
// 256 threads = 256 queries; online softmax (single pass); K/V staged in smem
// in 144-key chunks (36 KB -> multiple blocks/SM). Zero-padded K/V rows outside
// the image still contribute exp(bias) to the denominator (reference semantics).
__global__ void __launch_bounds__(256) attn_kernel(
    const float* __restrict__ q, const float* __restrict__ kv,
    const float* __restrict__ bias, float* __restrict__ out)
{
    __shared__ float ks[CHUNK * 32];
    __shared__ float vs[CHUNK * 32];

    const int wi   = blockIdx.x;      // 0..63 : b*16 + wy*4 + wx
    const int head = blockIdx.y;      // 0..5
    const int b  = wi >> 4;
    const int wy = (wi >> 2) & 3;
    const int wx = wi & 3;
    const int qi = threadIdx.x;

    // this thread's query (scaled), padded to 32
    const int iy = qi >> 4, ix = qi & 15;
    const int gy = wy * WS + iy, gx = wx * WS + ix;
    const float* qp = q + ((size_t)(b * 4096 + gy * 64 + gx)) * C_DIM + head * DHEAD;
    float qv[32];
    #pragma unroll
    for (int dd = 0; dd < DHEAD; dd++) qv[dd] = qp[dd] * 0.18257418583505537f; // 30^-0.5
    qv[30] = 0.f; qv[31] = 0.f;

    const float* bp = bias + (size_t)head * NKEY * NQ + qi;   // [ki][qi]

    float m = -1e30f, l = 0.f;
    float acc[32];
    #pragma unroll
    for (int u = 0; u < 32; u++) acc[u] = 0.f;

    for (int c0 = 0; c0 < NKEY; c0 += CHUNK) {
        __syncthreads();
        // stage K/V chunk
        for (int idx = qi; idx < CHUNK * 32; idx += 256) {
            int j  = (idx >> 5) + c0;
            int dd = idx & 31;
            int jy = j / OWS;
            int jx = j - jy * OWS;
            int ky = wy * WS - 4 + jy;
            int kx = wx * WS - 4 + jx;
            float kval = 0.f, vval = 0.f;
            if (dd < DHEAD && (unsigned)ky < 64u && (unsigned)kx < 64u) {
                const float* p = kv + ((size_t)(b * 4096 + ky * 64 + kx)) * (2 * C_DIM)
                                   + head * DHEAD + dd;
                kval = p[0];
                vval = p[C_DIM];
            }
            ks[idx] = kval;
            vs[idx] = vval;
        }
        __syncthreads();

        for (int j = 0; j < CHUNK; j++) {
            const float4* kr = (const float4*)(ks + j * 32);
            float s0 = bp[(size_t)(c0 + j) * NQ];
            float s1 = 0.f, s2 = 0.f, s3 = 0.f;
            #pragma unroll
            for (int u = 0; u < 8; u += 4) {
                float4 ka = kr[u + 0];
                float4 kb = kr[u + 1];
                float4 kc = kr[u + 2];
                float4 kd = kr[u + 3];
                s0 = fmaf(qv[4*u+ 0], ka.x, s0); s1 = fmaf(qv[4*u+ 1], ka.y, s1);
                s2 = fmaf(qv[4*u+ 2], ka.z, s2); s3 = fmaf(qv[4*u+ 3], ka.w, s3);
                s0 = fmaf(qv[4*u+ 4], kb.x, s0); s1 = fmaf(qv[4*u+ 5], kb.y, s1);
                s2 = fmaf(qv[4*u+ 6], kb.z, s2); s3 = fmaf(qv[4*u+ 7], kb.w, s3);
                s0 = fmaf(qv[4*u+ 8], kc.x, s0); s1 = fmaf(qv[4*u+ 9], kc.y, s1);
                s2 = fmaf(qv[4*u+10], kc.z, s2); s3 = fmaf(qv[4*u+11], kc.w, s3);
                s0 = fmaf(qv[4*u+12], kd.x, s0); s1 = fmaf(qv[4*u+13], kd.y, s1);
                s2 = fmaf(qv[4*u+14], kd.z, s2); s3 = fmaf(qv[4*u+15], kd.w, s3);
            }
            float s = (s0 + s1) + (s2 + s3);

            float p;
            if (s <= m) {
                p = __expf(s - m);
            } else {
                float r = __expf(m - s);   // first key: exp(-huge) = 0, exact
                l *= r;
                #pragma unroll
                for (int u = 0; u < 32; u++) acc[u] *= r;
                m = s;
                p = 1.f;
            }
            l += p;

            const float4* vr = (const float4*)(vs + j * 32);
            #pragma unroll
            for (int u = 0; u < 8; u++) {
                float4 v4 = vr[u];
                acc[4*u+0] = fmaf(p, v4.x, acc[4*u+0]);
                acc[4*u+1] = fmaf(p, v4.y, acc[4*u+1]);
                acc[4*u+2] = fmaf(p, v4.z, acc[4*u+2]);
                acc[4*u+3] = fmaf(p, v4.w, acc[4*u+3]);
            }
        }
    }
    float inv = 1.f / l;

    // write directly in (b, h*w, c) layout (window_reverse fused)
    float* op = out + ((size_t)(b * 4096 + gy * 64 + gx)) * C_DIM + head * DHEAD;
    #pragma unroll
    for (int dd = 0; dd < DHEAD; dd++) op[dd] = acc[dd] * inv;
}

// ---------------- launch --------------------------------------------------
extern "C" void kernel_launch(void* const* d_in, const int* in_sizes, int n_in,
                              void* d_out, int out_size)
{
    const float* x      = (const float*)d_in[0];
    const float* y      = (const float*)d_in[1];
    const float* n1g    = (const float*)d_in[2];
    const float* n1b    = (const float*)d_in[3];
    const float* kv_w   = (const float*)d_in[4];
    const float* kv_b   = (const float*)d_in[5];
    const float* q_w    = (const float*)d_in[6];
    const float* q_b    = (const float*)d_in[7];
    const float* rpb    = (const float*)d_in[8];
    const float* proj_w = (const float*)d_in[9];
    const float* proj_b = (const float*)d_in[10];
    const float* n2g    = (const float*)d_in[11];
    const float* n2b    = (const float*)d_in[12];
    const float* fc1_w  = (const float*)d_in[13];
    const float* fc1_b  = (const float*)d_in[14];
    const float* fc2_w  = (const float*)d_in[15];
    const float* fc2_b  = (const float*)d_in[16];
    const int*   rpi    = (const int*)d_in[17];
    float* outp = (float*)d_out;

    float *xn, *yn, *kvp, *qp, *attnp, *xop, *xn2p, *h1p, *biasp;
    cudaGetSymbolAddress((void**)&xn,    g_xn);
    cudaGetSymbolAddress((void**)&yn,    g_yn);
    cudaGetSymbolAddress((void**)&kvp,   g_kv);
    cudaGetSymbolAddress((void**)&qp,    g_q);
    cudaGetSymbolAddress((void**)&attnp, g_attn);
    cudaGetSymbolAddress((void**)&xop,   g_xo);
    cudaGetSymbolAddress((void**)&xn2p,  g_xn2);
    cudaGetSymbolAddress((void**)&h1p,   g_h1);
    cudaGetSymbolAddress((void**)&biasp, g_bias);

    // LN(x), LN(y)
    ln_kernel<<<M_ROWS / 8, 256>>>(x, n1g, n1b, xn);
    ln_kernel<<<M_ROWS / 8, 256>>>(y, n1g, n1b, yn);

    // bias table
    bias_kernel<<<(NQ * NKEY + 255) / 256, 256>>>(rpi, rpb, biasp);

    // kv = xn @ kv_w^T + kv_b   (N=360 -> BN=128, 3 tiles)
    gemm_kernel<128, 0><<<dim3(3, M_ROWS / 128), 256>>>(xn, kv_w, kv_b, nullptr, kvp,
                                                        M_ROWS, 2 * C_DIM, C_DIM);
    // q = yn @ q_w^T + q_b      (N=180 -> BN=64, 3 tiles)
    gemm_kernel<64, 0><<<dim3(3, M_ROWS / 128), 128>>>(yn, q_w, q_b, nullptr, qp,
                                                       M_ROWS, C_DIM, C_DIM);

    // windowed attention
    attn_kernel<<<dim3(64, NHEAD), 256>>>(qp, kvp, biasp, attnp);

    // xo = attn @ proj_w^T + proj_b + x
    gemm_kernel<64, 1><<<dim3(3, M_ROWS / 128), 128>>>(attnp, proj_w, proj_b, x, xop,
                                                       M_ROWS, C_DIM, C_DIM);

    // LN2
    ln_kernel<<<M_ROWS / 8, 256>>>(xop, n2g, n2b, xn2p);

    // h1 = gelu(xn2 @ fc1_w^T + fc1_b)   (N=720 -> BN=128, 6 tiles)
    gemm_kernel<128, 2><<<dim3(6, M_ROWS / 128), 256>>>(xn2p, fc1_w, fc1_b, nullptr, h1p,
                                                        M_ROWS, 4 * C_DIM, C_DIM);

    // out = h1 @ fc2_w^T + fc2_b + xo   (N=180, K=720 -> BN=64)
    gemm_kernel<64, 1><<<dim3(3, M_ROWS / 128), 128>>>(h1p, fc2_w, fc2_b, xop, outp,
                                                       M_ROWS, C_DIM, 4 * C_DIM);
}

// round 3
// speedup vs baseline: 1.9065x; 1.3406x over previous
#include <cuda_runtime.h>
#include <math.h>
#include <stdint.h>

// Problem constants
#define M_ROWS 16384            // b * h * w = 4*64*64
#define C_DIM  180
#define NHEAD  6
#define DHEAD  30
#define WS     16
#define OWS    24
#define NKEY   (OWS*OWS)        // 576
#define NQ     (WS*WS)          // 256
#define CHUNK  144              // 576 = 4*144 ; K/V smem per chunk = 36 KB

// ---------------- scratch (device globals; no allocation allowed) -----------
__device__ float g_xn  [M_ROWS * C_DIM];
__device__ float g_yn  [M_ROWS * C_DIM];
__device__ float g_kv  [M_ROWS * 2 * C_DIM];
__device__ float g_q   [M_ROWS * C_DIM];
__device__ float g_attn[M_ROWS * C_DIM];
__device__ float g_xo  [M_ROWS * C_DIM];
__device__ float g_xn2 [M_ROWS * C_DIM];
__device__ float g_h1  [M_ROWS * 4 * C_DIM];
__device__ float g_bias[NHEAD * NKEY * NQ];   // [head][ki][qi]

// ---------------- tf32 helpers ----------------------------------------------
__device__ __forceinline__ float to_tf32(float x) {
    uint32_t r;
    asm("cvt.rna.tf32.f32 %0, %1;" : "=r"(r) : "f"(x));
    return __uint_as_float(r);
}

__device__ __forceinline__ void mma_tf32(float c[4], const uint32_t a[4], const uint32_t b[2]) {
    asm volatile(
        "mma.sync.aligned.m16n8k8.row.col.f32.tf32.tf32.f32 "
        "{%0,%1,%2,%3},{%4,%5,%6,%7},{%8,%9},{%0,%1,%2,%3};"
        : "+f"(c[0]), "+f"(c[1]), "+f"(c[2]), "+f"(c[3])
        : "r"(a[0]), "r"(a[1]), "r"(a[2]), "r"(a[3]), "r"(b[0]), "r"(b[1]));
}

// ---------------- LayerNorm: one warp per row (C=180) -----------------------
__global__ void __launch_bounds__(256) ln_kernel(
    const float* __restrict__ x, const float* __restrict__ g,
    const float* __restrict__ b, float* __restrict__ out)
{
    int row  = blockIdx.x * 8 + (threadIdx.x >> 5);
    int lane = threadIdx.x & 31;
    const float* xr = x + (size_t)row * C_DIM;
    float v[6];
    float s = 0.f;
    #pragma unroll
    for (int i = 0; i < 6; i++) {
        int idx = lane + 32 * i;
        v[i] = (idx < C_DIM) ? xr[idx] : 0.f;
        s += v[i];
    }
    #pragma unroll
    for (int o = 16; o > 0; o >>= 1) s += __shfl_xor_sync(0xffffffffu, s, o);
    float mean = s * (1.f / C_DIM);
    float s2 = 0.f;
    #pragma unroll
    for (int i = 0; i < 6; i++) {
        int idx = lane + 32 * i;
        float d = (idx < C_DIM) ? (v[i] - mean) : 0.f;
        s2 += d * d;
    }
    #pragma unroll
    for (int o = 16; o > 0; o >>= 1) s2 += __shfl_xor_sync(0xffffffffu, s2, o);
    float r = rsqrtf(s2 * (1.f / C_DIM) + 1e-5f);
    float* orow = out + (size_t)row * C_DIM;
    #pragma unroll
    for (int i = 0; i < 6; i++) {
        int idx = lane + 32 * i;
        if (idx < C_DIM) orow[idx] = (v[i] - mean) * r * g[idx] + b[idx];
    }
}

// ---------------- bias precompute: biasT[h][ki][qi] = rpb[rpi[qi,ki], h] ----
__global__ void __launch_bounds__(256) bias_kernel(
    const int* __restrict__ rpi, const float* __restrict__ rpb,
    float* __restrict__ biasT)
{
    int idx = blockIdx.x * 256 + threadIdx.x;   // over NQ*NKEY
    if (idx >= NQ * NKEY) return;
    int qi = idx / NKEY;
    int ki = idx - qi * NKEY;
    int r = rpi[idx];
    #pragma unroll
    for (int h = 0; h < NHEAD; h++)
        biasT[((size_t)h * NKEY + ki) * NQ + qi] = rpb[r * NHEAD + h];
}

// ---------------- tensor-core GEMM: C[M,N] = A[M,K] @ W[N,K]^T + bias -------
// mma.sync m16n8k8 tf32. Block tile 128x64, BK=36 (padded to 40 in smem,
// cols 36..39 zero). 256 threads = 8 warps, warp grid 4(M) x 2(N),
// warp tile 32x32 = 2 M-atoms x 4 N-atoms.
// K is a multiple of 36 (180, 720); M a multiple of 128.
// EP: 0 = none, 1 = +res, 2 = exact GELU
template<int EP>
__global__ void __launch_bounds__(256) gemm_tc(
    const float* __restrict__ A, const float* __restrict__ W,
    const float* __restrict__ bias, const float* __restrict__ res,
    float* __restrict__ C, int M, int N, int K)
{
    __shared__ float As[128 * 40];
    __shared__ float Ws[64 * 40];

    const int t    = threadIdx.x;
    const int warp = t >> 5;
    const int lane = t & 31;
    const int wm   = (warp >> 1) * 32;     // 0,32,64,96
    const int wn   = (warp & 1) * 32;      // 0,32
    const int gid  = lane >> 2;            // 0..7
    const int tig  = lane & 3;             // 0..3
    const int bm   = blockIdx.y * 128;
    const int bn   = blockIdx.x * 64;

    // zero the pad columns 36..39 once (visible after the mid-loop sync)
    for (int i = t; i < 192; i += 256) {
        float* base = (i < 128) ? &As[i * 40] : &Ws[(i - 128) * 40];
        base[36] = 0.f; base[37] = 0.f; base[38] = 0.f; base[39] = 0.f;
    }

    float c[2][4][4];
    #pragma unroll
    for (int mi = 0; mi < 2; mi++)
        #pragma unroll
        for (int ni = 0; ni < 4; ni++)
            #pragma unroll
            for (int u = 0; u < 4; u++) c[mi][ni][u] = 0.f;

    for (int k0 = 0; k0 < K; k0 += 36) {
        __syncthreads();   // previous chunk fully consumed
        // stage A tile (128 x 36), tf32-rounded
        #pragma unroll
        for (int i = 0; i < 5; i++) {
            int idx = t + i * 256;
            if (idx < 1152) {
                int r = idx / 9, c4 = idx - r * 9;
                float4 v = *(const float4*)(A + (size_t)(bm + r) * K + k0 + c4 * 4);
                float* d = &As[r * 40 + c4 * 4];
                d[0] = to_tf32(v.x); d[1] = to_tf32(v.y);
                d[2] = to_tf32(v.z); d[3] = to_tf32(v.w);
            }
        }
        // stage W tile (64 x 36), tf32-rounded, zero rows beyond N
        #pragma unroll
        for (int i = 0; i < 3; i++) {
            int idx = t + i * 256;
            if (idx < 576) {
                int r = idx / 9, c4 = idx - r * 9;
                int n = bn + r;
                float4 v = make_float4(0.f, 0.f, 0.f, 0.f);
                if (n < N) v = *(const float4*)(W + (size_t)n * K + k0 + c4 * 4);
                float* d = &Ws[r * 40 + c4 * 4];
                d[0] = to_tf32(v.x); d[1] = to_tf32(v.y);
                d[2] = to_tf32(v.z); d[3] = to_tf32(v.w);
            }
        }
        __syncthreads();

        #pragma unroll
        for (int k8 = 0; k8 < 5; k8++) {
            const int kk = k8 * 8;
            uint32_t a[2][4], b[4][2];
            #pragma unroll
            for (int mi = 0; mi < 2; mi++) {
                const float* ap = &As[(wm + mi * 16 + gid) * 40 + kk + tig];
                a[mi][0] = __float_as_uint(ap[0]);
                a[mi][1] = __float_as_uint(ap[8 * 40]);
                a[mi][2] = __float_as_uint(ap[4]);
                a[mi][3] = __float_as_uint(ap[8 * 40 + 4]);
            }
            #pragma unroll
            for (int ni = 0; ni < 4; ni++) {
                const float* bp = &Ws[(wn + ni * 8 + gid) * 40 + kk + tig];
                b[ni][0] = __float_as_uint(bp[0]);
                b[ni][1] = __float_as_uint(bp[4]);
            }
            #pragma unroll
            for (int mi = 0; mi < 2; mi++)
                #pragma unroll
                for (int ni = 0; ni < 4; ni++)
                    mma_tf32(c[mi][ni], a[mi], b[ni]);
        }
    }

    // epilogue: c0,c1 at (row, col..col+1), c2,c3 at (row+8, ...)
    #pragma unroll
    for (int mi = 0; mi < 2; mi++) {
        int row = bm + wm + mi * 16 + gid;
        #pragma unroll
        for (int ni = 0; ni < 4; ni++) {
            int col = bn + wn + ni * 8 + tig * 2;
            if (col < N) {   // N even, col even -> col+1 < N too
                float v0 = c[mi][ni][0] + bias[col];
                float v1 = c[mi][ni][1] + bias[col + 1];
                float v2 = c[mi][ni][2] + bias[col];
                float v3 = c[mi][ni][3] + bias[col + 1];
                if (EP == 1) {
                    v0 += res[(size_t)row * N + col];
                    v1 += res[(size_t)row * N + col + 1];
                    v2 += res[(size_t)(row + 8) * N + col];
                    v3 += res[(size_t)(row + 8) * N + col + 1];
                }
                if (EP == 2) {
                    v0 = 0.5f * v0 * (1.f + erff(v0 * 0.70710678118654752f));
                    v1 = 0.5f * v1 * (1.f + erff(v1 * 0.70710678118654752f));
                    v2 = 0.5f * v2 * (1.f + erff(v2 * 0.70710678118654752f));
                    v3 = 0.5f * v3 * (1.f + erff(v3 * 0.70710678118654752f));
                }
                *(float2*)(C + (size_t)row * N + col)       = make_float2(v0, v1);
                *(float2*)(C + (size_t)(row + 8) * N + col) = make_float2(v2, v3);
            }
        }
    }
}

// ---------------- window attention: one block per (window, head) ------------
// 256 threads = 256 queries; online softmax (single pass); K/V staged in smem
// in 144-key chunks. Zero-padded K/V rows outside the image still contribute
// exp(bias) to the denominator (reference unfold-after-pad semantics).
__global__ void __launch_bounds__(256) attn_kernel(
    const float* __restrict__ q, const float* __restrict__ kv,
    const float* __restrict__ bias, float* __restrict__ out)
{
    __shared__ float ks[CHUNK * 32];
    __shared__ float vs[CHUNK * 32];

    const int wi   = blockIdx.x;      // 0..63 : b*16 + wy*4 + wx
    const int head = blockIdx.y;      // 0..5
    const int b  = wi >> 4;
    const int wy = (wi >> 2) & 3;
    const int wx = wi & 3;
    const int qi = threadIdx.x;

    const int iy = qi >> 4, ix = qi & 15;
    const int gy = wy * WS + iy, gx = wx * WS + ix;
    const float* qp = q + ((size_t)(b * 4096 + gy * 64 + gx)) * C_DIM + head * DHEAD;
    float qv[32];
    #pragma unroll
    for (int dd = 0; dd < DHEAD; dd++) qv[dd] = qp[dd] * 0.18257418583505537f; // 30^-0.5
    qv[30] = 0.f; qv[31] = 0.f;

    const float* bp = bias + (size_t)head * NKEY * NQ + qi;   // [ki][qi]

    float m = -1e30f, l = 0.f;
    float acc[32];
    #pragma unroll
    for (int u = 0; u < 32; u++) acc[u] = 0.f;

    for (int c0 = 0; c0 < NKEY; c0 += CHUNK) {
        __syncthreads();
        for (int idx = qi; idx < CHUNK * 32; idx += 256) {
            int j  = (idx >> 5) + c0;
            int dd = idx & 31;
            int jy = j / OWS;
            int jx = j - jy * OWS;
            int ky = wy * WS - 4 + jy;
            int kx = wx * WS - 4 + jx;
            float kval = 0.f, vval = 0.f;
            if (dd < DHEAD && (unsigned)ky < 64u && (unsigned)kx < 64u) {
                const float* p = kv + ((size_t)(b * 4096 + ky * 64 + kx)) * (2 * C_DIM)
                                   + head * DHEAD + dd;
                kval = p[0];
                vval = p[C_DIM];
            }
            ks[idx] = kval;
            vs[idx] = vval;
        }
        __syncthreads();

        for (int j = 0; j < CHUNK; j++) {
            const float4* kr = (const float4*)(ks + j * 32);
            float s0 = bp[(size_t)(c0 + j) * NQ];
            float s1 = 0.f, s2 = 0.f, s3 = 0.f;
            #pragma unroll
            for (int u = 0; u < 8; u += 4) {
                float4 ka = kr[u + 0];
                float4 kb = kr[u + 1];
                float4 kc = kr[u + 2];
                float4 kd = kr[u + 3];
                s0 = fmaf(qv[4*u+ 0], ka.x, s0); s1 = fmaf(qv[4*u+ 1], ka.y, s1);
                s2 = fmaf(qv[4*u+ 2], ka.z, s2); s3 = fmaf(qv[4*u+ 3], ka.w, s3);
                s0 = fmaf(qv[4*u+ 4], kb.x, s0); s1 = fmaf(qv[4*u+ 5], kb.y, s1);
                s2 = fmaf(qv[4*u+ 6], kb.z, s2); s3 = fmaf(qv[4*u+ 7], kb.w, s3);
                s0 = fmaf(qv[4*u+ 8], kc.x, s0); s1 = fmaf(qv[4*u+ 9], kc.y, s1);
                s2 = fmaf(qv[4*u+10], kc.z, s2); s3 = fmaf(qv[4*u+11], kc.w, s3);
                s0 = fmaf(qv[4*u+12], kd.x, s0); s1 = fmaf(qv[4*u+13], kd.y, s1);
                s2 = fmaf(qv[4*u+14], kd.z, s2); s3 = fmaf(qv[4*u+15], kd.w, s3);
            }
            float s = (s0 + s1) + (s2 + s3);

            float p;
            if (s <= m) {
                p = __expf(s - m);
            } else {
                float r = __expf(m - s);
                l *= r;
                #pragma unroll
                for (int u = 0; u < 32; u++) acc[u] *= r;
                m = s;
                p = 1.f;
            }
            l += p;

            const float4* vr = (const float4*)(vs + j * 32);
            #pragma unroll
            for (int u = 0; u < 8; u++) {
                float4 v4 = vr[u];
                acc[4*u+0] = fmaf(p, v4.x, acc[4*u+0]);
                acc[4*u+1] = fmaf(p, v4.y, acc[4*u+1]);
                acc[4*u+2] = fmaf(p, v4.z, acc[4*u+2]);
                acc[4*u+3] = fmaf(p, v4.w, acc[4*u+3]);
            }
        }
    }
    float inv = 1.f / l;

    float* op = out + ((size_t)(b * 4096 + gy * 64 + gx)) * C_DIM + head * DHEAD;
    #pragma unroll
    for (int dd = 0; dd < DHEAD; dd++) op[dd] = acc[dd] * inv;
}

// ---------------- launch --------------------------------------------------
extern "C" void kernel_launch(void* const* d_in, const int* in_sizes, int n_in,
                              void* d_out, int out_size)
{
    const float* x      = (const float*)d_in[0];
    const float* y      = (const float*)d_in[1];
    const float* n1g    = (const float*)d_in[2];
    const float* n1b    = (const float*)d_in[3];
    const float* kv_w   = (const float*)d_in[4];
    const float* kv_b   = (const float*)d_in[5];
    const float* q_w    = (const float*)d_in[6];
    const float* q_b    = (const float*)d_in[7];
    const float* rpb    = (const float*)d_in[8];
    const float* proj_w = (const float*)d_in[9];
    const float* proj_b = (const float*)d_in[10];
    const float* n2g    = (const float*)d_in[11];
    const float* n2b    = (const float*)d_in[12];
    const float* fc1_w  = (const float*)d_in[13];
    const float* fc1_b  = (const float*)d_in[14];
    const float* fc2_w  = (const float*)d_in[15];
    const float* fc2_b  = (const float*)d_in[16];
    const int*   rpi    = (const int*)d_in[17];
    float* outp = (float*)d_out;

    float *xn, *yn, *kvp, *qp, *attnp, *xop, *xn2p, *h1p, *biasp;
    cudaGetSymbolAddress((void**)&xn,    g_xn);
    cudaGetSymbolAddress((void**)&yn,    g_yn);
    cudaGetSymbolAddress((void**)&kvp,   g_kv);
    cudaGetSymbolAddress((void**)&qp,    g_q);
    cudaGetSymbolAddress((void**)&attnp, g_attn);
    cudaGetSymbolAddress((void**)&xop,   g_xo);
    cudaGetSymbolAddress((void**)&xn2p,  g_xn2);
    cudaGetSymbolAddress((void**)&h1p,   g_h1);
    cudaGetSymbolAddress((void**)&biasp, g_bias);

    // LN(x), LN(y)
    ln_kernel<<<M_ROWS / 8, 256>>>(x, n1g, n1b, xn);
    ln_kernel<<<M_ROWS / 8, 256>>>(y, n1g, n1b, yn);

    // bias table
    bias_kernel<<<(NQ * NKEY + 255) / 256, 256>>>(rpi, rpb, biasp);

    // kv = xn @ kv_w^T + kv_b   (N=360 -> 6 tiles)
    gemm_tc<0><<<dim3(6, M_ROWS / 128), 256>>>(xn, kv_w, kv_b, nullptr, kvp,
                                               M_ROWS, 2 * C_DIM, C_DIM);
    // q = yn @ q_w^T + q_b      (N=180 -> 3 tiles)
    gemm_tc<0><<<dim3(3, M_ROWS / 128), 256>>>(yn, q_w, q_b, nullptr, qp,
                                               M_ROWS, C_DIM, C_DIM);

    // windowed attention
    attn_kernel<<<dim3(64, NHEAD), 256>>>(qp, kvp, biasp, attnp);

    // xo = attn @ proj_w^T + proj_b + x
    gemm_tc<1><<<dim3(3, M_ROWS / 128), 256>>>(attnp, proj_w, proj_b, x, xop,
                                               M_ROWS, C_DIM, C_DIM);

    // LN2
    ln_kernel<<<M_ROWS / 8, 256>>>(xop, n2g, n2b, xn2p);

    // h1 = gelu(xn2 @ fc1_w^T + fc1_b)   (N=720 -> 12 tiles)
    gemm_tc<2><<<dim3(12, M_ROWS / 128), 256>>>(xn2p, fc1_w, fc1_b, nullptr, h1p,
                                                M_ROWS, 4 * C_DIM, C_DIM);

    // out = h1 @ fc2_w^T + fc2_b + xo   (N=180, K=720)
    gemm_tc<1><<<dim3(3, M_ROWS / 128), 256>>>(h1p, fc2_w, fc2_b, xop, outp,
                                               M_ROWS, C_DIM, 4 * C_DIM);
}

// round 4
// speedup vs baseline: 3.1857x; 1.6710x over previous
#include <cuda_runtime.h>
#include <math.h>
#include <stdint.h>

// Problem constants
#define M_ROWS 16384            // b * h * w = 4*64*64
#define C_DIM  180
#define NHEAD  6
#define DHEAD  30
#define WS     16
#define OWS    24
#define NKEY   (OWS*OWS)        // 576
#define NQ     (WS*WS)          // 256
#define KC     64               // keys per attention chunk (576 = 9*64)

// ---------------- scratch (device globals; no allocation allowed) -----------
__device__ float g_xn  [M_ROWS * C_DIM];
__device__ float g_yn  [M_ROWS * C_DIM];
__device__ float g_kv  [M_ROWS * 2 * C_DIM];
__device__ float g_q   [M_ROWS * C_DIM];
__device__ float g_attn[M_ROWS * C_DIM];
__device__ float g_xo  [M_ROWS * C_DIM];
__device__ float g_xn2 [M_ROWS * C_DIM];
__device__ float g_h1  [M_ROWS * 4 * C_DIM];
__device__ float g_bias[NHEAD * NKEY * NQ];   // [head][ki][qi]

// ---------------- tf32 helpers ----------------------------------------------
__device__ __forceinline__ float to_tf32(float x) {
    uint32_t r;
    asm("cvt.rna.tf32.f32 %0, %1;" : "=r"(r) : "f"(x));
    return __uint_as_float(r);
}
__device__ __forceinline__ uint32_t to_tf32u(float x) {
    uint32_t r;
    asm("cvt.rna.tf32.f32 %0, %1;" : "=r"(r) : "f"(x));
    return r;
}

__device__ __forceinline__ void mma_tf32(float c[4], const uint32_t a[4], const uint32_t b[2]) {
    asm volatile(
        "mma.sync.aligned.m16n8k8.row.col.f32.tf32.tf32.f32 "
        "{%0,%1,%2,%3},{%4,%5,%6,%7},{%8,%9},{%0,%1,%2,%3};"
        : "+f"(c[0]), "+f"(c[1]), "+f"(c[2]), "+f"(c[3])
        : "r"(a[0]), "r"(a[1]), "r"(a[2]), "r"(a[3]), "r"(b[0]), "r"(b[1]));
}

// ---------------- LayerNorm: one warp per row (C=180) -----------------------
__global__ void __launch_bounds__(256) ln_kernel(
    const float* __restrict__ x, const float* __restrict__ g,
    const float* __restrict__ b, float* __restrict__ out)
{
    int row  = blockIdx.x * 8 + (threadIdx.x >> 5);
    int lane = threadIdx.x & 31;
    const float* xr = x + (size_t)row * C_DIM;
    float v[6];
    float s = 0.f;
    #pragma unroll
    for (int i = 0; i < 6; i++) {
        int idx = lane + 32 * i;
        v[i] = (idx < C_DIM) ? xr[idx] : 0.f;
        s += v[i];
    }
    #pragma unroll
    for (int o = 16; o > 0; o >>= 1) s += __shfl_xor_sync(0xffffffffu, s, o);
    float mean = s * (1.f / C_DIM);
    float s2 = 0.f;
    #pragma unroll
    for (int i = 0; i < 6; i++) {
        int idx = lane + 32 * i;
        float d = (idx < C_DIM) ? (v[i] - mean) : 0.f;
        s2 += d * d;
    }
    #pragma unroll
    for (int o = 16; o > 0; o >>= 1) s2 += __shfl_xor_sync(0xffffffffu, s2, o);
    float r = rsqrtf(s2 * (1.f / C_DIM) + 1e-5f);
    float* orow = out + (size_t)row * C_DIM;
    #pragma unroll
    for (int i = 0; i < 6; i++) {
        int idx = lane + 32 * i;
        if (idx < C_DIM) orow[idx] = (v[i] - mean) * r * g[idx] + b[idx];
    }
}

// ---------------- bias precompute: biasT[h][ki][qi] = rpb[rpi[qi,ki], h] ----
__global__ void __launch_bounds__(256) bias_kernel(
    const int* __restrict__ rpi, const float* __restrict__ rpb,
    float* __restrict__ biasT)
{
    int idx = blockIdx.x * 256 + threadIdx.x;   // over NQ*NKEY
    if (idx >= NQ * NKEY) return;
    int qi = idx / NKEY;
    int ki = idx - qi * NKEY;
    int r = rpi[idx];
    #pragma unroll
    for (int h = 0; h < NHEAD; h++)
        biasT[((size_t)h * NKEY + ki) * NQ + qi] = rpb[r * NHEAD + h];
}

// ---------------- tensor-core GEMM: C[M,N] = A[M,K] @ W[N,K]^T + bias -------
// mma.sync m16n8k8 tf32. Block tile 128x64, BK=36 (padded to 40, cols 36..39
// zero). 256 threads = 8 warps, warp grid 4(M) x 2(N), warp tile 32x32.
// EP: 0 = none, 1 = +res, 2 = exact GELU
template<int EP>
__global__ void __launch_bounds__(256) gemm_tc(
    const float* __restrict__ A, const float* __restrict__ W,
    const float* __restrict__ bias, const float* __restrict__ res,
    float* __restrict__ C, int M, int N, int K)
{
    __shared__ float As[128 * 40];
    __shared__ float Ws[64 * 40];

    const int t    = threadIdx.x;
    const int warp = t >> 5;
    const int lane = t & 31;
    const int wm   = (warp >> 1) * 32;
    const int wn   = (warp & 1) * 32;
    const int gid  = lane >> 2;
    const int tig  = lane & 3;
    const int bm   = blockIdx.y * 128;
    const int bn   = blockIdx.x * 64;

    for (int i = t; i < 192; i += 256) {
        float* base = (i < 128) ? &As[i * 40] : &Ws[(i - 128) * 40];
        base[36] = 0.f; base[37] = 0.f; base[38] = 0.f; base[39] = 0.f;
    }

    float c[2][4][4];
    #pragma unroll
    for (int mi = 0; mi < 2; mi++)
        #pragma unroll
        for (int ni = 0; ni < 4; ni++)
            #pragma unroll
            for (int u = 0; u < 4; u++) c[mi][ni][u] = 0.f;

    for (int k0 = 0; k0 < K; k0 += 36) {
        __syncthreads();
        #pragma unroll
        for (int i = 0; i < 5; i++) {
            int idx = t + i * 256;
            if (idx < 1152) {
                int r = idx / 9, c4 = idx - r * 9;
                float4 v = *(const float4*)(A + (size_t)(bm + r) * K + k0 + c4 * 4);
                float* d = &As[r * 40 + c4 * 4];
                d[0] = to_tf32(v.x); d[1] = to_tf32(v.y);
                d[2] = to_tf32(v.z); d[3] = to_tf32(v.w);
            }
        }
        #pragma unroll
        for (int i = 0; i < 3; i++) {
            int idx = t + i * 256;
            if (idx < 576) {
                int r = idx / 9, c4 = idx - r * 9;
                int n = bn + r;
                float4 v = make_float4(0.f, 0.f, 0.f, 0.f);
                if (n < N) v = *(const float4*)(W + (size_t)n * K + k0 + c4 * 4);
                float* d = &Ws[r * 40 + c4 * 4];
                d[0] = to_tf32(v.x); d[1] = to_tf32(v.y);
                d[2] = to_tf32(v.z); d[3] = to_tf32(v.w);
            }
        }
        __syncthreads();

        #pragma unroll
        for (int k8 = 0; k8 < 5; k8++) {
            const int kk = k8 * 8;
            uint32_t a[2][4], b[4][2];
            #pragma unroll
            for (int mi = 0; mi < 2; mi++) {
                const float* ap = &As[(wm + mi * 16 + gid) * 40 + kk + tig];
                a[mi][0] = __float_as_uint(ap[0]);
                a[mi][1] = __float_as_uint(ap[8 * 40]);
                a[mi][2] = __float_as_uint(ap[4]);
                a[mi][3] = __float_as_uint(ap[8 * 40 + 4]);
            }
            #pragma unroll
            for (int ni = 0; ni < 4; ni++) {
                const float* bp = &Ws[(wn + ni * 8 + gid) * 40 + kk + tig];
                b[ni][0] = __float_as_uint(bp[0]);
                b[ni][1] = __float_as_uint(bp[4]);
            }
            #pragma unroll
            for (int mi = 0; mi < 2; mi++)
                #pragma unroll
                for (int ni = 0; ni < 4; ni++)
                    mma_tf32(c[mi][ni], a[mi], b[ni]);
        }
    }

    #pragma unroll
    for (int mi = 0; mi < 2; mi++) {
        int row = bm + wm + mi * 16 + gid;
        #pragma unroll
        for (int ni = 0; ni < 4; ni++) {
            int col = bn + wn + ni * 8 + tig * 2;
            if (col < N) {
                float v0 = c[mi][ni][0] + bias[col];
                float v1 = c[mi][ni][1] + bias[col + 1];
                float v2 = c[mi][ni][2] + bias[col];
                float v3 = c[mi][ni][3] + bias[col + 1];
                if (EP == 1) {
                    v0 += res[(size_t)row * N + col];
                    v1 += res[(size_t)row * N + col + 1];
                    v2 += res[(size_t)(row + 8) * N + col];
                    v3 += res[(size_t)(row + 8) * N + col + 1];
                }
                if (EP == 2) {
                    v0 = 0.5f * v0 * (1.f + erff(v0 * 0.70710678118654752f));
                    v1 = 0.5f * v1 * (1.f + erff(v1 * 0.70710678118654752f));
                    v2 = 0.5f * v2 * (1.f + erff(v2 * 0.70710678118654752f));
                    v3 = 0.5f * v3 * (1.f + erff(v3 * 0.70710678118654752f));
                }
                *(float2*)(C + (size_t)row * N + col)       = make_float2(v0, v1);
                *(float2*)(C + (size_t)(row + 8) * N + col) = make_float2(v2, v3);
            }
        }
    }
}

// ---------------- tensor-core window attention -------------------------------
// Block = (window, head); 8 warps x 32 queries. Keys in 64-chunks; flash-style
// online softmax. QK^T and P*V on mma.sync tf32. Padded keys have K=V=0 so
// S = bias only -> they contribute exp(bias) to the denominator (reference
// unfold-after-pad semantics).
__global__ void __launch_bounds__(256) attn_tc(
    const float* __restrict__ q, const float* __restrict__ kv,
    const float* __restrict__ bias, float* __restrict__ out)
{
    __shared__ float ks[KC * 32];
    __shared__ float vs[KC * 32];

    const int wi   = blockIdx.x;      // 0..63 : b*16 + wy*4 + wx
    const int head = blockIdx.y;
    const int b  = wi >> 4;
    const int wy = (wi >> 2) & 3;
    const int wx = wi & 3;
    const int t    = threadIdx.x;
    const int warp = t >> 5;
    const int lane = t & 31;
    const int gid  = lane >> 2;
    const int tig  = lane & 3;
    const int wq   = warp * 32;       // first query row of this warp

    // ---- load Q fragments once (scaled, tf32, d padded to 32) ----
    uint32_t qf[2][4][4];
    #pragma unroll
    for (int mi = 0; mi < 2; mi++) {
        int iy = (wq + mi * 16) >> 4;           // gid < 8 and gid+8 < 16 share iy
        int gy = wy * WS + iy;
        const float* q0 = q + ((size_t)(b * 4096 + gy * 64 + wx * WS + gid)) * C_DIM + head * DHEAD;
        const float* q1 = q + ((size_t)(b * 4096 + gy * 64 + wx * WS + gid + 8)) * C_DIM + head * DHEAD;
        #pragma unroll
        for (int kd = 0; kd < 4; kd++) {
            int d0 = kd * 8 + tig, d1 = d0 + 4;
            float a0 = (d0 < DHEAD) ? q0[d0] : 0.f;
            float a1 = (d0 < DHEAD) ? q1[d0] : 0.f;
            float a2 = (d1 < DHEAD) ? q0[d1] : 0.f;
            float a3 = (d1 < DHEAD) ? q1[d1] : 0.f;
            const float sc = 0.18257418583505537f;  // 30^-0.5
            qf[mi][kd][0] = to_tf32u(a0 * sc);
            qf[mi][kd][1] = to_tf32u(a1 * sc);
            qf[mi][kd][2] = to_tf32u(a2 * sc);
            qf[mi][kd][3] = to_tf32u(a3 * sc);
        }
    }

    const float* bp = bias + (size_t)head * NKEY * NQ;

    float m[2][2], l[2][2];
    #pragma unroll
    for (int mi = 0; mi < 2; mi++) { m[mi][0] = -1e30f; m[mi][1] = -1e30f; l[mi][0] = 0.f; l[mi][1] = 0.f; }
    float o[2][4][4];
    #pragma unroll
    for (int mi = 0; mi < 2; mi++)
        #pragma unroll
        for (int nj = 0; nj < 4; nj++)
            #pragma unroll
            for (int u = 0; u < 4; u++) o[mi][nj][u] = 0.f;

    for (int c0 = 0; c0 < NKEY; c0 += KC) {
        __syncthreads();
        // ---- stage K/V chunk (tf32), zero-fill pad region / d>=30 ----
        for (int idx = t; idx < KC * 32; idx += 256) {
            int j  = idx >> 5;
            int dd = idx & 31;
            int key = c0 + j;
            int jy = key / OWS;
            int jx = key - jy * OWS;
            int ky = wy * WS - 4 + jy;
            int kx = wx * WS - 4 + jx;
            float kval = 0.f, vval = 0.f;
            if (dd < DHEAD && (unsigned)ky < 64u && (unsigned)kx < 64u) {
                const float* p = kv + ((size_t)(b * 4096 + ky * 64 + kx)) * (2 * C_DIM)
                                   + head * DHEAD + dd;
                kval = to_tf32(p[0]);
                vval = to_tf32(p[C_DIM]);
            }
            ks[idx] = kval;
            vs[idx] = vval;
        }
        __syncthreads();

        // ---- S = Q K^T  (warp tile 32 x 64: 2 m-atoms x 8 n-atoms) ----
        float s[2][8][4];
        #pragma unroll
        for (int mi = 0; mi < 2; mi++)
            #pragma unroll
            for (int ni = 0; ni < 8; ni++)
                #pragma unroll
                for (int u = 0; u < 4; u++) s[mi][ni][u] = 0.f;

        #pragma unroll
        for (int kd = 0; kd < 4; kd++) {
            uint32_t bf[8][2];
            #pragma unroll
            for (int ni = 0; ni < 8; ni++) {
                const float* kp = &ks[(ni * 8 + gid) * 32 + kd * 8 + tig];
                bf[ni][0] = __float_as_uint(kp[0]);
                bf[ni][1] = __float_as_uint(kp[4]);
            }
            #pragma unroll
            for (int mi = 0; mi < 2; mi++)
                #pragma unroll
                for (int ni = 0; ni < 8; ni++)
                    mma_tf32(s[mi][ni], qf[mi][kd], bf[ni]);
        }

        // ---- + bias, online softmax ----
        #pragma unroll
        for (int mi = 0; mi < 2; mi++) {
            int q0 = wq + mi * 16 + gid;
            int q1 = q0 + 8;
            float mx0 = -1e30f, mx1 = -1e30f;
            #pragma unroll
            for (int ni = 0; ni < 8; ni++) {
                int kb = c0 + ni * 8 + 2 * tig;
                s[mi][ni][0] += bp[(size_t)kb * NQ + q0];
                s[mi][ni][1] += bp[(size_t)(kb + 1) * NQ + q0];
                s[mi][ni][2] += bp[(size_t)kb * NQ + q1];
                s[mi][ni][3] += bp[(size_t)(kb + 1) * NQ + q1];
                mx0 = fmaxf(mx0, fmaxf(s[mi][ni][0], s[mi][ni][1]));
                mx1 = fmaxf(mx1, fmaxf(s[mi][ni][2], s[mi][ni][3]));
            }
            mx0 = fmaxf(mx0, __shfl_xor_sync(0xffffffffu, mx0, 1));
            mx0 = fmaxf(mx0, __shfl_xor_sync(0xffffffffu, mx0, 2));
            mx1 = fmaxf(mx1, __shfl_xor_sync(0xffffffffu, mx1, 1));
            mx1 = fmaxf(mx1, __shfl_xor_sync(0xffffffffu, mx1, 2));
            float mn0 = fmaxf(m[mi][0], mx0);
            float mn1 = fmaxf(m[mi][1], mx1);
            float r0 = __expf(m[mi][0] - mn0);
            float r1 = __expf(m[mi][1] - mn1);
            m[mi][0] = mn0; m[mi][1] = mn1;
            l[mi][0] *= r0; l[mi][1] *= r1;
            #pragma unroll
            for (int nj = 0; nj < 4; nj++) {
                o[mi][nj][0] *= r0; o[mi][nj][1] *= r0;
                o[mi][nj][2] *= r1; o[mi][nj][3] *= r1;
            }
            float la0 = 0.f, la1 = 0.f;
            #pragma unroll
            for (int ni = 0; ni < 8; ni++) {
                s[mi][ni][0] = __expf(s[mi][ni][0] - mn0);
                s[mi][ni][1] = __expf(s[mi][ni][1] - mn0);
                s[mi][ni][2] = __expf(s[mi][ni][2] - mn1);
                s[mi][ni][3] = __expf(s[mi][ni][3] - mn1);
                la0 += s[mi][ni][0] + s[mi][ni][1];
                la1 += s[mi][ni][2] + s[mi][ni][3];
            }
            la0 += __shfl_xor_sync(0xffffffffu, la0, 1);
            la0 += __shfl_xor_sync(0xffffffffu, la0, 2);
            la1 += __shfl_xor_sync(0xffffffffu, la1, 1);
            la1 += __shfl_xor_sync(0xffffffffu, la1, 2);
            l[mi][0] += la0; l[mi][1] += la1;
        }

        // ---- O += P V : convert P (C-frag) -> A-frag via quad shuffles ----
        const int srcA = (lane & ~3) | (tig >> 1);
        const int srcB = srcA + 2;
        const bool oddc = (tig & 1);
        #pragma unroll
        for (int kk8 = 0; kk8 < 8; kk8++) {
            uint32_t ap[2][4];
            #pragma unroll
            for (int mi = 0; mi < 2; mi++) {
                float p0 = s[mi][kk8][0], p1 = s[mi][kk8][1];
                float p2 = s[mi][kk8][2], p3 = s[mi][kk8][3];
                float v00 = __shfl_sync(0xffffffffu, p0, srcA);
                float v01 = __shfl_sync(0xffffffffu, p1, srcA);
                float v10 = __shfl_sync(0xffffffffu, p2, srcA);
                float v11 = __shfl_sync(0xffffffffu, p3, srcA);
                float v20 = __shfl_sync(0xffffffffu, p0, srcB);
                float v21 = __shfl_sync(0xffffffffu, p1, srcB);
                float v30 = __shfl_sync(0xffffffffu, p2, srcB);
                float v31 = __shfl_sync(0xffffffffu, p3, srcB);
                ap[mi][0] = to_tf32u(oddc ? v01 : v00);
                ap[mi][1] = to_tf32u(oddc ? v11 : v10);
                ap[mi][2] = to_tf32u(oddc ? v21 : v20);
                ap[mi][3] = to_tf32u(oddc ? v31 : v30);
            }
            #pragma unroll
            for (int nj = 0; nj < 4; nj++) {
                uint32_t bv[2];
                const float* vp = &vs[(kk8 * 8 + tig) * 32 + nj * 8 + gid];
                bv[0] = __float_as_uint(vp[0]);
                bv[1] = __float_as_uint(vp[4 * 32]);
                #pragma unroll
                for (int mi = 0; mi < 2; mi++)
                    mma_tf32(o[mi][nj], ap[mi], bv);
            }
        }
    }

    // ---- normalize + write (window_reverse fused) ----
    #pragma unroll
    for (int mi = 0; mi < 2; mi++) {
        float inv0 = 1.f / l[mi][0];
        float inv1 = 1.f / l[mi][1];
        int iy = (wq + mi * 16) >> 4;
        int gy = wy * WS + iy;
        float* o0 = out + ((size_t)(b * 4096 + gy * 64 + wx * WS + gid)) * C_DIM + head * DHEAD;
        float* o1 = out + ((size_t)(b * 4096 + gy * 64 + wx * WS + gid + 8)) * C_DIM + head * DHEAD;
        #pragma unroll
        for (int nj = 0; nj < 4; nj++) {
            int d = nj * 8 + 2 * tig;
            if (d < DHEAD) {
                *(float2*)(o0 + d) = make_float2(o[mi][nj][0] * inv0, o[mi][nj][1] * inv0);
                *(float2*)(o1 + d) = make_float2(o[mi][nj][2] * inv1, o[mi][nj][3] * inv1);
            }
        }
    }
}

// ---------------- launch --------------------------------------------------
extern "C" void kernel_launch(void* const* d_in, const int* in_sizes, int n_in,
                              void* d_out, int out_size)
{
    const float* x      = (const float*)d_in[0];
    const float* y      = (const float*)d_in[1];
    const float* n1g    = (const float*)d_in[2];
    const float* n1b    = (const float*)d_in[3];
    const float* kv_w   = (const float*)d_in[4];
    const float* kv_b   = (const float*)d_in[5];
    const float* q_w    = (const float*)d_in[6];
    const float* q_b    = (const float*)d_in[7];
    const float* rpb    = (const float*)d_in[8];
    const float* proj_w = (const float*)d_in[9];
    const float* proj_b = (const float*)d_in[10];
    const float* n2g    = (const float*)d_in[11];
    const float* n2b    = (const float*)d_in[12];
    const float* fc1_w  = (const float*)d_in[13];
    const float* fc1_b  = (const float*)d_in[14];
    const float* fc2_w  = (const float*)d_in[15];
    const float* fc2_b  = (const float*)d_in[16];
    const int*   rpi    = (const int*)d_in[17];
    float* outp = (float*)d_out;

    float *xn, *yn, *kvp, *qp, *attnp, *xop, *xn2p, *h1p, *biasp;
    cudaGetSymbolAddress((void**)&xn,    g_xn);
    cudaGetSymbolAddress((void**)&yn,    g_yn);
    cudaGetSymbolAddress((void**)&kvp,   g_kv);
    cudaGetSymbolAddress((void**)&qp,    g_q);
    cudaGetSymbolAddress((void**)&attnp, g_attn);
    cudaGetSymbolAddress((void**)&xop,   g_xo);
    cudaGetSymbolAddress((void**)&xn2p,  g_xn2);
    cudaGetSymbolAddress((void**)&h1p,   g_h1);
    cudaGetSymbolAddress((void**)&biasp, g_bias);

    // LN(x), LN(y)
    ln_kernel<<<M_ROWS / 8, 256>>>(x, n1g, n1b, xn);
    ln_kernel<<<M_ROWS / 8, 256>>>(y, n1g, n1b, yn);

    // bias table
    bias_kernel<<<(NQ * NKEY + 255) / 256, 256>>>(rpi, rpb, biasp);

    // kv = xn @ kv_w^T + kv_b
    gemm_tc<0><<<dim3(6, M_ROWS / 128), 256>>>(xn, kv_w, kv_b, nullptr, kvp,
                                               M_ROWS, 2 * C_DIM, C_DIM);
    // q = yn @ q_w^T + q_b
    gemm_tc<0><<<dim3(3, M_ROWS / 128), 256>>>(yn, q_w, q_b, nullptr, qp,
                                               M_ROWS, C_DIM, C_DIM);

    // windowed attention (tensor cores)
    attn_tc<<<dim3(64, NHEAD), 256>>>(qp, kvp, biasp, attnp);

    // xo = attn @ proj_w^T + proj_b + x
    gemm_tc<1><<<dim3(3, M_ROWS / 128), 256>>>(attnp, proj_w, proj_b, x, xop,
                                               M_ROWS, C_DIM, C_DIM);

    // LN2
    ln_kernel<<<M_ROWS / 8, 256>>>(xop, n2g, n2b, xn2p);

    // h1 = gelu(xn2 @ fc1_w^T + fc1_b)
    gemm_tc<2><<<dim3(12, M_ROWS / 128), 256>>>(xn2p, fc1_w, fc1_b, nullptr, h1p,
                                                M_ROWS, 4 * C_DIM, C_DIM);

    // out = h1 @ fc2_w^T + fc2_b + xo
    gemm_tc<1><<<dim3(3, M_ROWS / 128), 256>>>(h1p, fc2_w, fc2_b, xop, outp,
                                               M_ROWS, C_DIM, 4 * C_DIM);
}

// round 5
// speedup vs baseline: 4.2454x; 1.3326x over previous
#include <cuda_runtime.h>
#include <math.h>
#include <stdint.h>

// Problem constants
#define M_ROWS 16384            // b * h * w = 4*64*64
#define C_DIM  180
#define NHEAD  6
#define DHEAD  30
#define WS     16
#define OWS    24
#define NKEY   (OWS*OWS)        // 576
#define NQ     (WS*WS)          // 256
#define KC     64               // keys per attention chunk (576 = 9*64)

#define GSTRIDE 44              // GEMM smem row stride (44 mod 32 = 12 -> conflict-free frags)
#define ASTRIDE 36              // attention K/V smem row stride
#define ABUF (128 * GSTRIDE)
#define WBUF (64 * GSTRIDE)

// ---------------- scratch (device globals; no allocation allowed) -----------
__device__ float g_xn  [M_ROWS * C_DIM];
__device__ float g_yn  [M_ROWS * C_DIM];
__device__ float g_kv  [M_ROWS * 2 * C_DIM];
__device__ float g_q   [M_ROWS * C_DIM];
__device__ float g_attn[M_ROWS * C_DIM];
__device__ float g_xo  [M_ROWS * C_DIM];
__device__ float g_xn2 [M_ROWS * C_DIM];
__device__ float g_h1  [M_ROWS * 4 * C_DIM];
__device__ float g_bias[NHEAD * NKEY * NQ];   // [head][ki][qi]

// ---------------- mma / async helpers ----------------------------------------
__device__ __forceinline__ void mma_tf32(float c[4], const uint32_t a[4], const uint32_t b[2]) {
    asm volatile(
        "mma.sync.aligned.m16n8k8.row.col.f32.tf32.tf32.f32 "
        "{%0,%1,%2,%3},{%4,%5,%6,%7},{%8,%9},{%0,%1,%2,%3};"
        : "+f"(c[0]), "+f"(c[1]), "+f"(c[2]), "+f"(c[3])
        : "r"(a[0]), "r"(a[1]), "r"(a[2]), "r"(a[3]), "r"(b[0]), "r"(b[1]));
}

__device__ __forceinline__ void cp_async16(float* smem_dst, const float* gmem_src, bool pred) {
    uint32_t s = (uint32_t)__cvta_generic_to_shared(smem_dst);
    int sz = pred ? 16 : 0;
    asm volatile("cp.async.cg.shared.global [%0], [%1], 16, %2;"
                 :: "r"(s), "l"(gmem_src), "r"(sz));
}
__device__ __forceinline__ void cp_commit() {
    asm volatile("cp.async.commit_group;");
}
template<int N>
__device__ __forceinline__ void cp_wait() {
    asm volatile("cp.async.wait_group %0;" :: "n"(N));
}

// ---------------- LayerNorm: one warp per row (C=180) -----------------------
__global__ void __launch_bounds__(256) ln_kernel(
    const float* __restrict__ x, const float* __restrict__ g,
    const float* __restrict__ b, float* __restrict__ out)
{
    int row  = blockIdx.x * 8 + (threadIdx.x >> 5);
    int lane = threadIdx.x & 31;
    const float* xr = x + (size_t)row * C_DIM;
    float v[6];
    float s = 0.f;
    #pragma unroll
    for (int i = 0; i < 6; i++) {
        int idx = lane + 32 * i;
        v[i] = (idx < C_DIM) ? xr[idx] : 0.f;
        s += v[i];
    }
    #pragma unroll
    for (int o = 16; o > 0; o >>= 1) s += __shfl_xor_sync(0xffffffffu, s, o);
    float mean = s * (1.f / C_DIM);
    float s2 = 0.f;
    #pragma unroll
    for (int i = 0; i < 6; i++) {
        int idx = lane + 32 * i;
        float d = (idx < C_DIM) ? (v[i] - mean) : 0.f;
        s2 += d * d;
    }
    #pragma unroll
    for (int o = 16; o > 0; o >>= 1) s2 += __shfl_xor_sync(0xffffffffu, s2, o);
    float r = rsqrtf(s2 * (1.f / C_DIM) + 1e-5f);
    float* orow = out + (size_t)row * C_DIM;
    #pragma unroll
    for (int i = 0; i < 6; i++) {
        int idx = lane + 32 * i;
        if (idx < C_DIM) orow[idx] = (v[i] - mean) * r * g[idx] + b[idx];
    }
}

// ---------------- bias precompute: biasT[h][ki][qi] = rpb[rpi[qi,ki], h] ----
__global__ void __launch_bounds__(256) bias_kernel(
    const int* __restrict__ rpi, const float* __restrict__ rpb,
    float* __restrict__ biasT)
{
    int idx = blockIdx.x * 256 + threadIdx.x;   // over NQ*NKEY
    if (idx >= NQ * NKEY) return;
    int qi = idx / NKEY;
    int ki = idx - qi * NKEY;
    int r = rpi[idx];
    #pragma unroll
    for (int h = 0; h < NHEAD; h++)
        biasT[((size_t)h * NKEY + ki) * NQ + qi] = rpb[r * NHEAD + h];
}

// ---------------- tensor-core GEMM: C[M,N] = A[M,K] @ W[N,K]^T + bias -------
// mma.sync m16n8k8 tf32 (raw fp32 operands; HW truncates to tf32).
// Block tile 128x64, BK=36 (smem stride 44; cols 36..39 zeroed).
// cp.async double-buffered staging. 8 warps, warp grid 4(M) x 2(N).
// EP: 0 = none, 1 = +res, 2 = exact GELU
template<int EP>
__global__ void __launch_bounds__(256) gemm_tc(
    const float* __restrict__ A, const float* __restrict__ W,
    const float* __restrict__ bias, const float* __restrict__ res,
    float* __restrict__ C, int M, int N, int K)
{
    extern __shared__ float sm[];
    float* Ab[2] = { sm, sm + ABUF };
    float* Wb[2] = { sm + 2 * ABUF, sm + 2 * ABUF + WBUF };

    const int t    = threadIdx.x;
    const int warp = t >> 5;
    const int lane = t & 31;
    const int wm   = (warp >> 1) * 32;
    const int wn   = (warp & 1) * 32;
    const int gid  = lane >> 2;
    const int tig  = lane & 3;
    const int bm   = blockIdx.y * 128;
    const int bn   = blockIdx.x * 64;
    const int nk   = K / 36;

    // zero pad columns 36..39 of both buffers (never written by cp.async)
    for (int i = t; i < 384; i += 256) {
        int bufi = (i >= 192);
        int r = i - bufi * 192;
        float* base = (r < 128) ? &Ab[bufi][r * GSTRIDE] : &Wb[bufi][(r - 128) * GSTRIDE];
        base[36] = 0.f; base[37] = 0.f; base[38] = 0.f; base[39] = 0.f;
    }

    auto stage = [&](int k0, int bufi) {
        float* a = Ab[bufi];
        float* w = Wb[bufi];
        #pragma unroll
        for (int i = 0; i < 5; i++) {
            int idx = t + i * 256;
            if (idx < 1152) {
                int r = idx / 9, c4 = idx - r * 9;
                cp_async16(&a[r * GSTRIDE + c4 * 4],
                           A + (size_t)(bm + r) * K + k0 + c4 * 4, true);
            }
        }
        #pragma unroll
        for (int i = 0; i < 3; i++) {
            int idx = t + i * 256;
            if (idx < 576) {
                int r = idx / 9, c4 = idx - r * 9;
                int n = bn + r;
                bool ok = (n < N);
                const float* src = W + (size_t)(ok ? n : 0) * K + k0 + c4 * 4;
                cp_async16(&w[r * GSTRIDE + c4 * 4], src, ok);
            }
        }
    };

    float c[2][4][4];
    #pragma unroll
    for (int mi = 0; mi < 2; mi++)
        #pragma unroll
        for (int ni = 0; ni < 4; ni++)
            #pragma unroll
            for (int u = 0; u < 4; u++) c[mi][ni][u] = 0.f;

    stage(0, 0);
    cp_commit();

    for (int i = 0; i < nk; i++) {
        if (i + 1 < nk) {
            stage((i + 1) * 36, (i + 1) & 1);
            cp_commit();
            cp_wait<1>();
        } else {
            cp_wait<0>();
        }
        __syncthreads();

        const float* As = Ab[i & 1];
        const float* Ws = Wb[i & 1];
        #pragma unroll
        for (int k8 = 0; k8 < 5; k8++) {
            const int kk = k8 * 8;
            uint32_t a[2][4], b[4][2];
            #pragma unroll
            for (int mi = 0; mi < 2; mi++) {
                const float* ap = &As[(wm + mi * 16 + gid) * GSTRIDE + kk + tig];
                a[mi][0] = __float_as_uint(ap[0]);
                a[mi][1] = __float_as_uint(ap[8 * GSTRIDE]);
                a[mi][2] = __float_as_uint(ap[4]);
                a[mi][3] = __float_as_uint(ap[8 * GSTRIDE + 4]);
            }
            #pragma unroll
            for (int ni = 0; ni < 4; ni++) {
                const float* bp = &Ws[(wn + ni * 8 + gid) * GSTRIDE + kk + tig];
                b[ni][0] = __float_as_uint(bp[0]);
                b[ni][1] = __float_as_uint(bp[4]);
            }
            #pragma unroll
            for (int mi = 0; mi < 2; mi++)
                #pragma unroll
                for (int ni = 0; ni < 4; ni++)
                    mma_tf32(c[mi][ni], a[mi], b[ni]);
        }
        __syncthreads();
    }

    #pragma unroll
    for (int mi = 0; mi < 2; mi++) {
        int row = bm + wm + mi * 16 + gid;
        #pragma unroll
        for (int ni = 0; ni < 4; ni++) {
            int col = bn + wn + ni * 8 + tig * 2;
            if (col < N) {
                float v0 = c[mi][ni][0] + bias[col];
                float v1 = c[mi][ni][1] + bias[col + 1];
                float v2 = c[mi][ni][2] + bias[col];
                float v3 = c[mi][ni][3] + bias[col + 1];
                if (EP == 1) {
                    v0 += res[(size_t)row * N + col];
                    v1 += res[(size_t)row * N + col + 1];
                    v2 += res[(size_t)(row + 8) * N + col];
                    v3 += res[(size_t)(row + 8) * N + col + 1];
                }
                if (EP == 2) {
                    v0 = 0.5f * v0 * (1.f + erff(v0 * 0.70710678118654752f));
                    v1 = 0.5f * v1 * (1.f + erff(v1 * 0.70710678118654752f));
                    v2 = 0.5f * v2 * (1.f + erff(v2 * 0.70710678118654752f));
                    v3 = 0.5f * v3 * (1.f + erff(v3 * 0.70710678118654752f));
                }
                *(float2*)(C + (size_t)row * N + col)       = make_float2(v0, v1);
                *(float2*)(C + (size_t)(row + 8) * N + col) = make_float2(v2, v3);
            }
        }
    }
}

// ---------------- tensor-core window attention -------------------------------
// Block = (window, head); 8 warps x 32 queries; 64-key chunks; flash-style
// online softmax. QK^T and P*V via mma.sync tf32 (raw fp32, HW truncation).
// Padded keys have K=V=0 so S = bias only (reference unfold-after-pad
// semantics preserved). K/V smem stride 36 -> conflict-free K-frag reads.
__global__ void __launch_bounds__(256) attn_tc(
    const float* __restrict__ q, const float* __restrict__ kv,
    const float* __restrict__ bias, float* __restrict__ out)
{
    __shared__ float ks[KC * ASTRIDE];
    __shared__ float vs[KC * ASTRIDE];

    const int wi   = blockIdx.x;      // 0..63 : b*16 + wy*4 + wx
    const int head = blockIdx.y;
    const int b  = wi >> 4;
    const int wy = (wi >> 2) & 3;
    const int wx = wi & 3;
    const int t    = threadIdx.x;
    const int warp = t >> 5;
    const int lane = t & 31;
    const int gid  = lane >> 2;
    const int tig  = lane & 3;
    const int wq   = warp * 32;       // first query row of this warp

    // ---- load Q fragments once (scaled, d padded to 32) ----
    uint32_t qf[2][4][4];
    #pragma unroll
    for (int mi = 0; mi < 2; mi++) {
        int iy = (wq + mi * 16) >> 4;
        int gy = wy * WS + iy;
        const float* q0 = q + ((size_t)(b * 4096 + gy * 64 + wx * WS + gid)) * C_DIM + head * DHEAD;
        const float* q1 = q + ((size_t)(b * 4096 + gy * 64 + wx * WS + gid + 8)) * C_DIM + head * DHEAD;
        #pragma unroll
        for (int kd = 0; kd < 4; kd++) {
            int d0 = kd * 8 + tig, d1 = d0 + 4;
            float a0 = (d0 < DHEAD) ? q0[d0] : 0.f;
            float a1 = (d0 < DHEAD) ? q1[d0] : 0.f;
            float a2 = (d1 < DHEAD) ? q0[d1] : 0.f;
            float a3 = (d1 < DHEAD) ? q1[d1] : 0.f;
            const float sc = 0.18257418583505537f;  // 30^-0.5
            qf[mi][kd][0] = __float_as_uint(a0 * sc);
            qf[mi][kd][1] = __float_as_uint(a1 * sc);
            qf[mi][kd][2] = __float_as_uint(a2 * sc);
            qf[mi][kd][3] = __float_as_uint(a3 * sc);
        }
    }

    const float* bp = bias + (size_t)head * NKEY * NQ;

    float m[2][2], l[2][2];
    #pragma unroll
    for (int mi = 0; mi < 2; mi++) { m[mi][0] = -1e30f; m[mi][1] = -1e30f; l[mi][0] = 0.f; l[mi][1] = 0.f; }
    float o[2][4][4];
    #pragma unroll
    for (int mi = 0; mi < 2; mi++)
        #pragma unroll
        for (int nj = 0; nj < 4; nj++)
            #pragma unroll
            for (int u = 0; u < 4; u++) o[mi][nj][u] = 0.f;

    for (int c0 = 0; c0 < NKEY; c0 += KC) {
        __syncthreads();
        for (int idx = t; idx < KC * 32; idx += 256) {
            int j  = idx >> 5;
            int dd = idx & 31;
            int key = c0 + j;
            int jy = key / OWS;
            int jx = key - jy * OWS;
            int ky = wy * WS - 4 + jy;
            int kx = wx * WS - 4 + jx;
            float kval = 0.f, vval = 0.f;
            if (dd < DHEAD && (unsigned)ky < 64u && (unsigned)kx < 64u) {
                const float* p = kv + ((size_t)(b * 4096 + ky * 64 + kx)) * (2 * C_DIM)
                                   + head * DHEAD + dd;
                kval = p[0];
                vval = p[C_DIM];
            }
            ks[j * ASTRIDE + dd] = kval;
            vs[j * ASTRIDE + dd] = vval;
        }
        __syncthreads();

        // ---- S = Q K^T ----
        float s[2][8][4];
        #pragma unroll
        for (int mi = 0; mi < 2; mi++)
            #pragma unroll
            for (int ni = 0; ni < 8; ni++)
                #pragma unroll
                for (int u = 0; u < 4; u++) s[mi][ni][u] = 0.f;

        #pragma unroll
        for (int kd = 0; kd < 4; kd++) {
            uint32_t bf[8][2];
            #pragma unroll
            for (int ni = 0; ni < 8; ni++) {
                const float* kp = &ks[(ni * 8 + gid) * ASTRIDE + kd * 8 + tig];
                bf[ni][0] = __float_as_uint(kp[0]);
                bf[ni][1] = __float_as_uint(kp[4]);
            }
            #pragma unroll
            for (int mi = 0; mi < 2; mi++)
                #pragma unroll
                for (int ni = 0; ni < 8; ni++)
                    mma_tf32(s[mi][ni], qf[mi][kd], bf[ni]);
        }

        // ---- + bias, online softmax ----
        #pragma unroll
        for (int mi = 0; mi < 2; mi++) {
            int q0 = wq + mi * 16 + gid;
            int q1 = q0 + 8;
            float mx0 = -1e30f, mx1 = -1e30f;
            #pragma unroll
            for (int ni = 0; ni < 8; ni++) {
                int kb = c0 + ni * 8 + 2 * tig;
                s[mi][ni][0] += bp[(size_t)kb * NQ + q0];
                s[mi][ni][1] += bp[(size_t)(kb + 1) * NQ + q0];
                s[mi][ni][2] += bp[(size_t)kb * NQ + q1];
                s[mi][ni][3] += bp[(size_t)(kb + 1) * NQ + q1];
                mx0 = fmaxf(mx0, fmaxf(s[mi][ni][0], s[mi][ni][1]));
                mx1 = fmaxf(mx1, fmaxf(s[mi][ni][2], s[mi][ni][3]));
            }
            mx0 = fmaxf(mx0, __shfl_xor_sync(0xffffffffu, mx0, 1));
            mx0 = fmaxf(mx0, __shfl_xor_sync(0xffffffffu, mx0, 2));
            mx1 = fmaxf(mx1, __shfl_xor_sync(0xffffffffu, mx1, 1));
            mx1 = fmaxf(mx1, __shfl_xor_sync(0xffffffffu, mx1, 2));
            float mn0 = fmaxf(m[mi][0], mx0);
            float mn1 = fmaxf(m[mi][1], mx1);
            float r0 = __expf(m[mi][0] - mn0);
            float r1 = __expf(m[mi][1] - mn1);
            m[mi][0] = mn0; m[mi][1] = mn1;
            l[mi][0] *= r0; l[mi][1] *= r1;
            #pragma unroll
            for (int nj = 0; nj < 4; nj++) {
                o[mi][nj][0] *= r0; o[mi][nj][1] *= r0;
                o[mi][nj][2] *= r1; o[mi][nj][3] *= r1;
            }
            float la0 = 0.f, la1 = 0.f;
            #pragma unroll
            for (int ni = 0; ni < 8; ni++) {
                s[mi][ni][0] = __expf(s[mi][ni][0] - mn0);
                s[mi][ni][1] = __expf(s[mi][ni][1] - mn0);
                s[mi][ni][2] = __expf(s[mi][ni][2] - mn1);
                s[mi][ni][3] = __expf(s[mi][ni][3] - mn1);
                la0 += s[mi][ni][0] + s[mi][ni][1];
                la1 += s[mi][ni][2] + s[mi][ni][3];
            }
            la0 += __shfl_xor_sync(0xffffffffu, la0, 1);
            la0 += __shfl_xor_sync(0xffffffffu, la0, 2);
            la1 += __shfl_xor_sync(0xffffffffu, la1, 1);
            la1 += __shfl_xor_sync(0xffffffffu, la1, 2);
            l[mi][0] += la0; l[mi][1] += la1;
        }

        // ---- O += P V : convert P (C-frag) -> A-frag via quad shuffles ----
        const int srcA = (lane & ~3) | (tig >> 1);
        const int srcB = srcA + 2;
        const bool oddc = (tig & 1);
        #pragma unroll
        for (int kk8 = 0; kk8 < 8; kk8++) {
            uint32_t ap[2][4];
            #pragma unroll
            for (int mi = 0; mi < 2; mi++) {
                float p0 = s[mi][kk8][0], p1 = s[mi][kk8][1];
                float p2 = s[mi][kk8][2], p3 = s[mi][kk8][3];
                float v00 = __shfl_sync(0xffffffffu, p0, srcA);
                float v01 = __shfl_sync(0xffffffffu, p1, srcA);
                float v10 = __shfl_sync(0xffffffffu, p2, srcA);
                float v11 = __shfl_sync(0xffffffffu, p3, srcA);
                float v20 = __shfl_sync(0xffffffffu, p0, srcB);
                float v21 = __shfl_sync(0xffffffffu, p1, srcB);
                float v30 = __shfl_sync(0xffffffffu, p2, srcB);
                float v31 = __shfl_sync(0xffffffffu, p3, srcB);
                ap[mi][0] = __float_as_uint(oddc ? v01 : v00);
                ap[mi][1] = __float_as_uint(oddc ? v11 : v10);
                ap[mi][2] = __float_as_uint(oddc ? v21 : v20);
                ap[mi][3] = __float_as_uint(oddc ? v31 : v30);
            }
            #pragma unroll
            for (int nj = 0; nj < 4; nj++) {
                uint32_t bv[2];
                const float* vp = &vs[(kk8 * 8 + tig) * ASTRIDE + nj * 8 + gid];
                bv[0] = __float_as_uint(vp[0]);
                bv[1] = __float_as_uint(vp[4 * ASTRIDE]);
                #pragma unroll
                for (int mi = 0; mi < 2; mi++)
                    mma_tf32(o[mi][nj], ap[mi], bv);
            }
        }
    }

    // ---- normalize + write (window_reverse fused) ----
    #pragma unroll
    for (int mi = 0; mi < 2; mi++) {
        float inv0 = 1.f / l[mi][0];
        float inv1 = 1.f / l[mi][1];
        int iy = (wq + mi * 16) >> 4;
        int gy = wy * WS + iy;
        float* o0 = out + ((size_t)(b * 4096 + gy * 64 + wx * WS + gid)) * C_DIM + head * DHEAD;
        float* o1 = out + ((size_t)(b * 4096 + gy * 64 + wx * WS + gid + 8)) * C_DIM + head * DHEAD;
        #pragma unroll
        for (int nj = 0; nj < 4; nj++) {
            int d = nj * 8 + 2 * tig;
            if (d < DHEAD) {
                *(float2*)(o0 + d) = make_float2(o[mi][nj][0] * inv0, o[mi][nj][1] * inv0);
                *(float2*)(o1 + d) = make_float2(o[mi][nj][2] * inv1, o[mi][nj][3] * inv1);
            }
        }
    }
}

// ---------------- launch --------------------------------------------------
extern "C" void kernel_launch(void* const* d_in, const int* in_sizes, int n_in,
                              void* d_out, int out_size)
{
    const float* x      = (const float*)d_in[0];
    const float* y      = (const float*)d_in[1];
    const float* n1g    = (const float*)d_in[2];
    const float* n1b    = (const float*)d_in[3];
    const float* kv_w   = (const float*)d_in[4];
    const float* kv_b   = (const float*)d_in[5];
    const float* q_w    = (const float*)d_in[6];
    const float* q_b    = (const float*)d_in[7];
    const float* rpb    = (const float*)d_in[8];
    const float* proj_w = (const float*)d_in[9];
    const float* proj_b = (const float*)d_in[10];
    const float* n2g    = (const float*)d_in[11];
    const float* n2b    = (const float*)d_in[12];
    const float* fc1_w  = (const float*)d_in[13];
    const float* fc1_b  = (const float*)d_in[14];
    const float* fc2_w  = (const float*)d_in[15];
    const float* fc2_b  = (const float*)d_in[16];
    const int*   rpi    = (const int*)d_in[17];
    float* outp = (float*)d_out;

    float *xn, *yn, *kvp, *qp, *attnp, *xop, *xn2p, *h1p, *biasp;
    cudaGetSymbolAddress((void**)&xn,    g_xn);
    cudaGetSymbolAddress((void**)&yn,    g_yn);
    cudaGetSymbolAddress((void**)&kvp,   g_kv);
    cudaGetSymbolAddress((void**)&qp,    g_q);
    cudaGetSymbolAddress((void**)&attnp, g_attn);
    cudaGetSymbolAddress((void**)&xop,   g_xo);
    cudaGetSymbolAddress((void**)&xn2p,  g_xn2);
    cudaGetSymbolAddress((void**)&h1p,   g_h1);
    cudaGetSymbolAddress((void**)&biasp, g_bias);

    const int gemm_smem = (2 * ABUF + 2 * WBUF) * 4;   // 67584 bytes
    cudaFuncSetAttribute(gemm_tc<0>, cudaFuncAttributeMaxDynamicSharedMemorySize, gemm_smem);
    cudaFuncSetAttribute(gemm_tc<1>, cudaFuncAttributeMaxDynamicSharedMemorySize, gemm_smem);
    cudaFuncSetAttribute(gemm_tc<2>, cudaFuncAttributeMaxDynamicSharedMemorySize, gemm_smem);

    // LN(x), LN(y)
    ln_kernel<<<M_ROWS / 8, 256>>>(x, n1g, n1b, xn);
    ln_kernel<<<M_ROWS / 8, 256>>>(y, n1g, n1b, yn);

    // bias table
    bias_kernel<<<(NQ * NKEY + 255) / 256, 256>>>(rpi, rpb, biasp);

    // kv = xn @ kv_w^T + kv_b
    gemm_tc<0><<<dim3(6, M_ROWS / 128), 256, gemm_smem>>>(xn, kv_w, kv_b, nullptr, kvp,
                                                          M_ROWS, 2 * C_DIM, C_DIM);
    // q = yn @ q_w^T + q_b
    gemm_tc<0><<<dim3(3, M_ROWS / 128), 256, gemm_smem>>>(yn, q_w, q_b, nullptr, qp,
                                                          M_ROWS, C_DIM, C_DIM);

    // windowed attention (tensor cores)
    attn_tc<<<dim3(64, NHEAD), 256>>>(qp, kvp, biasp, attnp);

    // xo = attn @ proj_w^T + proj_b + x
    gemm_tc<1><<<dim3(3, M_ROWS / 128), 256, gemm_smem>>>(attnp, proj_w, proj_b, x, xop,
                                                          M_ROWS, C_DIM, C_DIM);

    // LN2
    ln_kernel<<<M_ROWS / 8, 256>>>(xop, n2g, n2b, xn2p);

    // h1 = gelu(xn2 @ fc1_w^T + fc1_b)
    gemm_tc<2><<<dim3(12, M_ROWS / 128), 256, gemm_smem>>>(xn2p, fc1_w, fc1_b, nullptr, h1p,
                                                           M_ROWS, 4 * C_DIM, C_DIM);

    // out = h1 @ fc2_w^T + fc2_b + xo
    gemm_tc<1><<<dim3(3, M_ROWS / 128), 256, gemm_smem>>>(h1p, fc2_w, fc2_b, xop, outp,
                                                          M_ROWS, C_DIM, 4 * C_DIM);
}